// round 2
// baseline (speedup 1.0000x reference)
#include <cuda_runtime.h>
#include <cuda_bf16.h>
#include <cstdint>

// Problem constants (from reference)
#define MAXN 100000
#define MAXE 1600000
#define FI   64
#define H    4
#define D    16
#define ED   5
#define NEG_SLOPE 0.2f

// ---------------- static device scratch (no allocations allowed) --------------
__device__ float  g_featp[MAXN * FI];        // [N,64] projected node feats (h-major: h*16+d)
__device__ float4 g_el[MAXN];                // [N,4] per-head left logit term
__device__ float4 g_er[MAXN];                // [N,4] per-head right logit term
__device__ float  g_ftfz[MAXN * H * 8];      // [N,4,8] = {z, ep0..ep4, pad, pad}
__device__ float  g_ft[MAXN * H * D];        // [N,4,16] unnormalized sum p*feat_p[src]

// sm_90+ vector reduction: 1 instruction = 4 float adds resolved at L2
__device__ __forceinline__ void red_add4(float* p, float a, float b, float c, float d) {
    unsigned long long g = (unsigned long long)__cvta_generic_to_global(p);
    asm volatile("red.global.add.v4.f32 [%0], {%1, %2, %3, %4};"
                 :: "l"(g), "f"(a), "f"(b), "f"(c), "f"(d) : "memory");
}

// ---------------- kernel 1: zero accumulators --------------------------------
__global__ void k_init(int N) {
    int t = blockIdx.x * blockDim.x + threadIdx.x;
    int nft = N * H * D;    // 6.4M
    int nfz = N * H * 8;    // 3.2M
    if (t < nft) g_ft[t] = 0.0f;
    else if (t < nft + nfz) g_ftfz[t - nft] = 0.0f;
}

// ---------------- kernel 2: node projection + el/er --------------------------
// 256 threads = 4 nodes/block; W_fc (64x64) staged in smem.
__global__ void k_nodeproj(const float* __restrict__ feat,
                           const float* __restrict__ W_fc,
                           const float* __restrict__ attn_l,
                           const float* __restrict__ attn_r, int N) {
    __shared__ float sW[FI * 64];
    __shared__ float sf[4][FI];
    int tid = threadIdx.x;
    #pragma unroll
    for (int i = tid; i < FI * 64; i += 256) sW[i] = W_fc[i];
    int nl = tid >> 6, j = tid & 63;
    int n = blockIdx.x * 4 + nl;
    if (n < N) sf[nl][j] = feat[n * FI + j];
    __syncthreads();
    if (n >= N) return;

    float acc = 0.0f;
    #pragma unroll
    for (int i = 0; i < FI; i++) acc += sf[nl][i] * sW[i * 64 + j];
    g_featp[n * 64 + j] = acc;

    // per-head dot with attn_l / attn_r via 16-lane butterfly
    int h = j >> 4, d = j & 15;
    float elp = acc * __ldg(&attn_l[h * D + d]);
    float erp = acc * __ldg(&attn_r[h * D + d]);
    #pragma unroll
    for (int off = 8; off; off >>= 1) {
        elp += __shfl_xor_sync(0xffffffffu, elp, off);
        erp += __shfl_xor_sync(0xffffffffu, erp, off);
    }
    if (d == 0) {
        ((float*)g_el)[n * 4 + h] = elp;
        ((float*)g_er)[n * 4 + h] = erp;
    }
}

// ---------------- kernel 3: FUSED edge pass ----------------------------------
// 4 threads per edge (one per head). Computes edge projection + logit + exp,
// then scatters unnormalized {p, p*edge_p, p*feat_p[src]} with red.global.v4.
// No segment-max: logits are O(+-7) here, exp(e)/sum(exp(e)) is exact in fp32.
__global__ void k_edge(const float* __restrict__ edge_fea,
                       const int* __restrict__ src,
                       const int* __restrict__ dst,
                       const float* __restrict__ W_edg,
                       const float* __restrict__ b_edg,
                       const float* __restrict__ attn_edg, int E) {
    __shared__ float sWe[ED * H * ED];   // 100
    __shared__ float sbe[H * ED];        // 20
    __shared__ float sae[H * ED];        // 20
    int tid = threadIdx.x;
    if (tid < 100) sWe[tid] = W_edg[tid];
    if (tid < 20)  { sbe[tid] = b_edg[tid]; sae[tid] = attn_edg[tid]; }
    __syncthreads();

    int gt = blockIdx.x * blockDim.x + tid;
    int e = gt >> 2, h = gt & 3;
    if (e >= E) return;
    int s = __ldg(&src[e]), d = __ldg(&dst[e]);

    // edge projection for this head: ep[k] = b + edge_fea[e,:] . W[:, h,k]
    float ef[ED];
    #pragma unroll
    for (int j = 0; j < ED; j++) ef[j] = __ldg(&edge_fea[e * ED + j]);
    float ep[ED], ee = 0.0f;
    #pragma unroll
    for (int k = 0; k < ED; k++) {
        float v = sbe[h * ED + k];
        #pragma unroll
        for (int j = 0; j < ED; j++) v += ef[j] * sWe[j * (H * ED) + h * ED + k];
        ep[k] = v;
        ee += v * sae[h * ED + k];
    }

    // logit -> leaky relu -> unnormalized softmax weight
    float x = ((const float*)g_el)[s * 4 + h] + ((const float*)g_er)[d * 4 + h] + ee;
    x = x > 0.0f ? x : NEG_SLOPE * x;
    float p = __expf(x);

    // scatter z and p*edge_p (6 floats -> 2 v4 REDs)
    float* fz = &g_ftfz[(d * H + h) * 8];
    red_add4(fz,     p,        p * ep[0], p * ep[1], p * ep[2]);
    red_add4(fz + 4, p * ep[3], p * ep[4], 0.0f,     0.0f);

    // gather feat_p[src] for this head (L2-resident, 25.6MB) and scatter
    const float4* fp = (const float4*)&g_featp[s * 64 + h * D];
    float* fo = &g_ft[(d * H + h) * D];
    #pragma unroll
    for (int i = 0; i < 4; i++) {
        float4 v = __ldg(&fp[i]);
        red_add4(fo + 4 * i, p * v.x, p * v.y, p * v.z, p * v.w);
    }
}

// ---------------- kernel 4: normalize + output GEMV ---------------------------
__global__ void k_output(const float* __restrict__ W_out,
                         const float* __restrict__ b_out,
                         const float* __restrict__ bias,
                         float* __restrict__ out, int N) {
    __shared__ float sW[(ED + D) * D];   // 336
    __shared__ float sb[D];
    __shared__ float sbias[H * D];
    int tid = threadIdx.x;
    for (int i = tid; i < (ED + D) * D; i += blockDim.x) sW[i] = W_out[i];
    if (tid < D) sb[tid] = b_out[tid];
    if (tid < H * D) sbias[tid] = bias[tid];
    __syncthreads();

    int gid = blockIdx.x * blockDim.x + tid;
    int n = gid >> 6;
    if (n >= N) return;
    int hd = gid & 63, h = hd >> 4, dd = hd & 15;

    const float* fz = &g_ftfz[(n * H + h) * 8];
    float z = fz[0];
    float inv = z > 0.0f ? 1.0f / z : 0.0f;

    float acc = sb[dd] + sbias[hd];
    #pragma unroll
    for (int k = 0; k < ED; k++)
        acc += fz[1 + k] * inv * sW[k * D + dd];
    const float* ftp = &g_ft[(n * H + h) * D];
    #pragma unroll
    for (int k = 0; k < D; k++)
        acc += ftp[k] * inv * sW[(ED + k) * D + dd];
    out[gid] = acc;
}

// ---------------- launch ------------------------------------------------------
extern "C" void kernel_launch(void* const* d_in, const int* in_sizes, int n_in,
                              void* d_out, int out_size) {
    const float* feat     = (const float*)d_in[0];
    const float* edge_fea = (const float*)d_in[1];
    const int*   src      = (const int*)  d_in[2];
    const int*   dst      = (const int*)  d_in[3];
    const float* W_fc     = (const float*)d_in[4];
    const float* W_edg    = (const float*)d_in[5];
    const float* b_edg    = (const float*)d_in[6];
    const float* attn_l   = (const float*)d_in[7];
    const float* attn_r   = (const float*)d_in[8];
    const float* attn_edg = (const float*)d_in[9];
    const float* W_out    = (const float*)d_in[10];
    const float* b_out    = (const float*)d_in[11];
    const float* bias     = (const float*)d_in[12];
    float* out = (float*)d_out;

    int N = in_sizes[0] / FI;
    int E = in_sizes[2];
    if (N > MAXN) N = MAXN;
    if (E > MAXE) E = MAXE;

    int initElems = N * H * D + N * H * 8;
    k_init<<<(initElems + 255) / 256, 256>>>(N);
    k_nodeproj<<<(N + 3) / 4, 256>>>(feat, W_fc, attn_l, attn_r, N);
    k_edge<<<(E * 4 + 255) / 256, 256>>>(edge_fea, src, dst, W_edg, b_edg, attn_edg, E);
    k_output<<<(N * 64 + 255) / 256, 256>>>(W_out, b_out, bias, out, N);
}

// round 3
// speedup vs baseline: 1.1047x; 1.1047x over previous
#include <cuda_runtime.h>
#include <cuda_bf16.h>
#include <cstdint>

#define MAXN 100000
#define MAXE 1600000
#define FI   64
#define H    4
#define D    16
#define ED   5
#define NEG_SLOPE 0.2f

// ---------------- static device scratch --------------------------------------
__device__ float  g_featp[MAXN * FI];     // [N,64] projected node feats (h*16+d)
__device__ float4 g_el[MAXN];             // [N,4]
__device__ float4 g_er[MAXN];             // [N,4]
// unified accumulator: per (n,h) a 24-float row: {z, s0..s4, pad, pad, ft0..ft15}
__device__ float4 g_acc[MAXN * H * 6];

// sm_90+ vector reductions resolved at L2
__device__ __forceinline__ void red_add4(float* p, float a, float b, float c, float d) {
    unsigned long long g = (unsigned long long)__cvta_generic_to_global(p);
    asm volatile("red.global.add.v4.f32 [%0], {%1, %2, %3, %4};"
                 :: "l"(g), "f"(a), "f"(b), "f"(c), "f"(d) : "memory");
}
__device__ __forceinline__ void red_add2(float* p, float a, float b) {
    unsigned long long g = (unsigned long long)__cvta_generic_to_global(p);
    asm volatile("red.global.add.v2.f32 [%0], {%1, %2};"
                 :: "l"(g), "f"(a), "f"(b) : "memory");
}

// ---------------- kernel 1: zero accumulators (float4 stores) -----------------
__global__ void k_init(int N) {
    int t = blockIdx.x * blockDim.x + threadIdx.x;
    int n4 = N * H * 6;                       // 2.4M float4
    if (t < n4) g_acc[t] = make_float4(0.f, 0.f, 0.f, 0.f);
}

// ---------------- kernel 2: node projection + el/er ---------------------------
__global__ void k_nodeproj(const float* __restrict__ feat,
                           const float* __restrict__ W_fc,
                           const float* __restrict__ attn_l,
                           const float* __restrict__ attn_r, int N) {
    __shared__ float sW[FI * 64];
    __shared__ float sf[4][FI];
    int tid = threadIdx.x;
    #pragma unroll
    for (int i = tid; i < FI * 64; i += 256) sW[i] = W_fc[i];
    int nl = tid >> 6, j = tid & 63;
    int n = blockIdx.x * 4 + nl;
    if (n < N) sf[nl][j] = feat[n * FI + j];
    __syncthreads();
    if (n >= N) return;

    float acc = 0.0f;
    #pragma unroll
    for (int i = 0; i < FI; i++) acc += sf[nl][i] * sW[i * 64 + j];
    g_featp[n * 64 + j] = acc;

    int h = j >> 4, d = j & 15;
    float elp = acc * __ldg(&attn_l[h * D + d]);
    float erp = acc * __ldg(&attn_r[h * D + d]);
    #pragma unroll
    for (int off = 8; off; off >>= 1) {
        elp += __shfl_xor_sync(0xffffffffu, elp, off);
        erp += __shfl_xor_sync(0xffffffffu, erp, off);
    }
    if (d == 0) {
        ((float*)g_el)[n * 4 + h] = elp;
        ((float*)g_er)[n * 4 + h] = erp;
    }
}

// ---------------- kernel 3: FUSED edge pass -----------------------------------
// 4 threads/edge (one per head). Folded logit: ee = ef . w_h + c_h where
// w_h = W_edg[:,h,:] @ attn_edg[h], c_h = b_edg[h,:] . attn_edg[h].
// Scatters {p, p*ef} (v4+v2) and p*featp[src] (4x v4), unnormalized.
__global__ void k_edge(const float* __restrict__ edge_fea,
                       const int* __restrict__ src,
                       const int* __restrict__ dst,
                       const float* __restrict__ W_edg,
                       const float* __restrict__ b_edg,
                       const float* __restrict__ attn_edg, int E) {
    __shared__ float sw[H][ED];
    __shared__ float sc[H];
    int tid = threadIdx.x;
    if (tid < H * ED) {
        int h = tid / ED, j = tid % ED;
        float a = 0.0f;
        #pragma unroll
        for (int k = 0; k < ED; k++)
            a += W_edg[j * (H * ED) + h * ED + k] * attn_edg[h * ED + k];
        sw[h][j] = a;
    }
    if (tid < H) {
        float a = 0.0f;
        #pragma unroll
        for (int k = 0; k < ED; k++) a += b_edg[tid * ED + k] * attn_edg[tid * ED + k];
        sc[tid] = a;
    }
    __syncthreads();

    int gt = blockIdx.x * blockDim.x + tid;
    int e = gt >> 2, h = gt & 3;
    if (e >= E) return;
    int s = __ldg(&src[e]), d = __ldg(&dst[e]);

    float ef[ED];
    #pragma unroll
    for (int j = 0; j < ED; j++) ef[j] = __ldg(&edge_fea[e * ED + j]);

    float ee = sc[h];
    #pragma unroll
    for (int j = 0; j < ED; j++) ee += ef[j] * sw[h][j];

    float x = ((const float*)g_el)[s * 4 + h] + ((const float*)g_er)[d * 4 + h] + ee;
    x = x > 0.0f ? x : NEG_SLOPE * x;
    float p = __expf(x);

    float* row = (float*)&g_acc[(d * H + h) * 6];
    red_add4(row,     p,         p * ef[0], p * ef[1], p * ef[2]);
    red_add2(row + 4, p * ef[3], p * ef[4]);

    const float4* fp = (const float4*)&g_featp[s * 64 + h * D];
    #pragma unroll
    for (int i = 0; i < 4; i++) {
        float4 v = __ldg(&fp[i]);
        red_add4(row + 8 + 4 * i, p * v.x, p * v.y, p * v.z, p * v.w);
    }
}

// ---------------- kernel 4: normalize + W_edg fold + output GEMV --------------
// One thread per (n,h): 24-float coalesced row load, 16 outputs in registers.
__global__ void k_output(const float* __restrict__ W_edg,
                         const float* __restrict__ b_edg,
                         const float* __restrict__ W_out,
                         const float* __restrict__ b_out,
                         const float* __restrict__ bias,
                         float* __restrict__ out, int N) {
    __shared__ float sWo[(ED + D) * D];   // 336
    __shared__ float sWe[ED * H * ED];    // 100
    __shared__ float sbe[H * ED];         // 20
    __shared__ float sb[D];               // 16
    __shared__ float sbias[H * D];        // 64
    int tid = threadIdx.x;
    for (int i = tid; i < (ED + D) * D; i += 256) sWo[i] = W_out[i];
    if (tid < 100) sWe[tid] = W_edg[tid];
    if (tid < 20)  sbe[tid] = b_edg[tid];
    if (tid < D)   sb[tid] = b_out[tid];
    if (tid < H * D) sbias[tid] = bias[tid];
    __syncthreads();

    int nh = blockIdx.x * blockDim.x + tid;
    if (nh >= N * H) return;
    int h = nh & 3;

    const float4* r4 = &g_acc[nh * 6];
    float4 a0 = r4[0], a1 = r4[1], a2 = r4[2], a3 = r4[3], a4 = r4[4], a5 = r4[5];
    float z = a0.x;
    float inv = z > 0.0f ? 1.0f / z : 0.0f;
    float s0 = a0.y, s1 = a0.z, s2 = a0.w, s3 = a1.x, s4 = a1.y;
    float ft[D] = {a2.x, a2.y, a2.z, a2.w, a3.x, a3.y, a3.z, a3.w,
                   a4.x, a4.y, a4.z, a4.w, a5.x, a5.y, a5.z, a5.w};

    // reconstruct normalized ep sums: (sum p*ef)@W_edg[:,h,:] + z*b, then *inv
    float ep[ED];
    #pragma unroll
    for (int k = 0; k < ED; k++) {
        float v = z * sbe[h * ED + k];
        v += s0 * sWe[0 * (H * ED) + h * ED + k];
        v += s1 * sWe[1 * (H * ED) + h * ED + k];
        v += s2 * sWe[2 * (H * ED) + h * ED + k];
        v += s3 * sWe[3 * (H * ED) + h * ED + k];
        v += s4 * sWe[4 * (H * ED) + h * ED + k];
        ep[k] = v * inv;
    }
    #pragma unroll
    for (int k = 0; k < D; k++) ft[k] *= inv;

    float o[D];
    #pragma unroll
    for (int dd = 0; dd < D; dd++) o[dd] = sb[dd] + sbias[h * D + dd];
    #pragma unroll
    for (int k = 0; k < ED; k++)
        #pragma unroll
        for (int dd = 0; dd < D; dd++) o[dd] += ep[k] * sWo[k * D + dd];
    #pragma unroll
    for (int k = 0; k < D; k++)
        #pragma unroll
        for (int dd = 0; dd < D; dd++) o[dd] += ft[k] * sWo[(ED + k) * D + dd];

    float4* op = (float4*)&out[nh * D];
    op[0] = make_float4(o[0],  o[1],  o[2],  o[3]);
    op[1] = make_float4(o[4],  o[5],  o[6],  o[7]);
    op[2] = make_float4(o[8],  o[9],  o[10], o[11]);
    op[3] = make_float4(o[12], o[13], o[14], o[15]);
}

// ---------------- launch ------------------------------------------------------
extern "C" void kernel_launch(void* const* d_in, const int* in_sizes, int n_in,
                              void* d_out, int out_size) {
    const float* feat     = (const float*)d_in[0];
    const float* edge_fea = (const float*)d_in[1];
    const int*   src      = (const int*)  d_in[2];
    const int*   dst      = (const int*)  d_in[3];
    const float* W_fc     = (const float*)d_in[4];
    const float* W_edg    = (const float*)d_in[5];
    const float* b_edg    = (const float*)d_in[6];
    const float* attn_l   = (const float*)d_in[7];
    const float* attn_r   = (const float*)d_in[8];
    const float* attn_edg = (const float*)d_in[9];
    const float* W_out    = (const float*)d_in[10];
    const float* b_out    = (const float*)d_in[11];
    const float* bias     = (const float*)d_in[12];
    float* out = (float*)d_out;

    int N = in_sizes[0] / FI;
    int E = in_sizes[2];
    if (N > MAXN) N = MAXN;
    if (E > MAXE) E = MAXE;

    k_init<<<(N * H * 6 + 255) / 256, 256>>>(N);
    k_nodeproj<<<(N + 3) / 4, 256>>>(feat, W_fc, attn_l, attn_r, N);
    k_edge<<<(E * 4 + 255) / 256, 256>>>(edge_fea, src, dst, W_edg, b_edg, attn_edg, E);
    k_output<<<(N * H + 255) / 256, 256>>>(W_edg, b_edg, W_out, b_out, bias, out, N);
}